// round 1
// baseline (speedup 1.0000x reference)
#include <cuda_runtime.h>
#include <cuda_bf16.h>
#include <math.h>

// ---------------------------------------------------------------- dims
#define Dd 512
#define Hh 512
#define Ff 2048
#define Ll 2
#define Ss 4
#define Pp 2
#define Tt 3
#define Ee 10
#define NEe 6
#define Gg 64
#define Bb 4096
#define NG 18   // T * NE groups

// ---------------------------------------------------------------- scratch (device globals; no allocs allowed)
__device__ float g_h [(size_t)NG * Bb * Hh];   // 144 MB  running hidden state
__device__ float g_t1[(size_t)NG * Bb * Hh];   // 144 MB
__device__ float g_t2[(size_t)NG * Bb * Hh];   // 144 MB
__device__ float g_f [(size_t)NG * Bb * Ff];   // 576 MB  FFN intermediate
__device__ float g_o [(size_t)NG * Bb * Hh];   // 144 MB  expert outputs
__device__ float g_gh  [(size_t)Tt * Bb * Gg];
__device__ float g_gate[(size_t)Tt * Bb * NEe];
__device__ float g_cat [(size_t)Bb * Tt * Dd];
__device__ float g_fuse[(size_t)Bb * 2 * Dd];

// ---------------------------------------------------------------- f32x2 packed helpers (full-rate fp32 on sm_103a)
__device__ __forceinline__ unsigned long long pack2(float lo, float hi) {
    unsigned long long r;
    asm("mov.b64 %0, {%1, %2};" : "=l"(r) : "f"(lo), "f"(hi));
    return r;
}
__device__ __forceinline__ void fma2(unsigned long long& d, unsigned long long a, unsigned long long b) {
    asm("fma.rn.f32x2 %0, %1, %2, %3;" : "=l"(d) : "l"(a), "l"(b), "l"(d));
}
__device__ __forceinline__ float2 unpack2(unsigned long long v) {
    float2 r;
    asm("mov.b64 {%0, %1}, %2;" : "=f"(r.x), "=f"(r.y) : "l"(v));
    return r;
}

__device__ __forceinline__ float warp_sum(float v) {
    v += __shfl_xor_sync(0xffffffffu, v, 16);
    v += __shfl_xor_sync(0xffffffffu, v, 8);
    v += __shfl_xor_sync(0xffffffffu, v, 4);
    v += __shfl_xor_sync(0xffffffffu, v, 2);
    v += __shfl_xor_sync(0xffffffffu, v, 1);
    return v;
}

__device__ __forceinline__ int expert_of_group(int g) {
    int task = g / NEe;
    int n = g % NEe;
    return (n < Ss) ? n : Ss + task * Pp + (n - Ss);
}

// ---------------------------------------------------------------- generic grouped GEMM
// C[g] = epi( A[g] @ W[expert(g)] + bias[expert(g)] (+ Res[g]) )
// A row-major [M,K], W row-major [K,N], C row-major [M,N].
// aMode/resMode: 0 -> offset 0, 1 -> (g/NE)*stride (by task), 2 -> g*stride.
// wMode: 0 -> index 0, 1 -> expert_of_group(g), 2 -> g.
// EPI: 0 none, 1 exact gelu, 2 relu
#define BM 128
#define BN 128
#define BKK 8

template <int EPI>
__global__ __launch_bounds__(256, 2)
void gemm_kernel(const float* __restrict__ A, long aStride, int aMode,
                 const float* __restrict__ W, long wStride, int wMode,
                 const float* __restrict__ bias, long bStride,
                 const float* __restrict__ Res, long resStride, int resMode,
                 float* __restrict__ C, long cStride,
                 int M, int N, int K)
{
    const int g    = blockIdx.z;
    const int task = g / NEe;
    int widx = 0;
    if (wMode == 1) widx = expert_of_group(g);
    else if (wMode == 2) widx = g;
    long aoff = 0;
    if (aMode == 1) aoff = (long)task * aStride;
    else if (aMode == 2) aoff = (long)g * aStride;

    const float* Ag = A + aoff;
    const float* Wg = W + (long)widx * wStride;
    const float* Bg = bias ? bias + (long)widx * bStride : nullptr;

    __shared__ float As[BKK][BM];
    __shared__ float Bs[BKK][BN];

    const int tid  = threadIdx.x;
    const int warp = tid >> 5;
    const int lane = tid & 31;
    // warp tiling: 4x2 warps of 32x64; lane -> 4x8 grid of 8x8 tiles
    const int rowC = (warp >> 1) * 32 + (lane >> 3) * 8;
    const int colC = (warp & 1) * 64 + (lane & 7) * 8;

    const int blockRow = blockIdx.y * BM;
    const int blockCol = blockIdx.x * BN;

    // global->shared mapping
    const int arow = tid >> 1;          // 0..127
    const int acol = (tid & 1) * 4;     // 0 or 4
    const int brow = tid >> 5;          // 0..7
    const int bcol = (lane) * 4;        // 0..124

    unsigned long long acc[8][4];
#pragma unroll
    for (int i = 0; i < 8; i++)
#pragma unroll
        for (int j = 0; j < 4; j++) acc[i][j] = 0ULL;

    const float* Aptr = Ag + (long)(blockRow + arow) * K + acol;
    const float* Wptr = Wg + (long)brow * N + blockCol + bcol;
    const bool bLoadOk = (blockCol + bcol) < N;

    for (int kt = 0; kt < K; kt += BKK) {
        float4 av = *(const float4*)Aptr;
        Aptr += BKK;
        float4 bv = make_float4(0.f, 0.f, 0.f, 0.f);
        if (bLoadOk) bv = *(const float4*)Wptr;
        Wptr += (long)BKK * N;

        As[acol + 0][arow] = av.x;
        As[acol + 1][arow] = av.y;
        As[acol + 2][arow] = av.z;
        As[acol + 3][arow] = av.w;
        *(float4*)&Bs[brow][bcol] = bv;
        __syncthreads();

#pragma unroll
        for (int k = 0; k < BKK; k++) {
            float4 a0 = *(const float4*)&As[k][rowC];
            float4 a1 = *(const float4*)&As[k][rowC + 4];
            float4 b0 = *(const float4*)&Bs[k][colC];
            float4 b1 = *(const float4*)&Bs[k][colC + 4];
            unsigned long long bb[4] = { pack2(b0.x, b0.y), pack2(b0.z, b0.w),
                                         pack2(b1.x, b1.y), pack2(b1.z, b1.w) };
            float a[8] = { a0.x, a0.y, a0.z, a0.w, a1.x, a1.y, a1.z, a1.w };
#pragma unroll
            for (int i = 0; i < 8; i++) {
                unsigned long long aa = pack2(a[i], a[i]);
#pragma unroll
                for (int j = 0; j < 4; j++) fma2(acc[i][j], aa, bb[j]);
            }
        }
        __syncthreads();
    }

    // ---------------- epilogue
    const int ccol = blockCol + colC;
    if (ccol >= N) return;   // N is a multiple of 8; whole 8-col chunk in/out

    float bvals[8];
    if (Bg) {
        float4 q0 = *(const float4*)(Bg + ccol);
        float4 q1 = *(const float4*)(Bg + ccol + 4);
        bvals[0] = q0.x; bvals[1] = q0.y; bvals[2] = q0.z; bvals[3] = q0.w;
        bvals[4] = q1.x; bvals[5] = q1.y; bvals[6] = q1.z; bvals[7] = q1.w;
    } else {
#pragma unroll
        for (int j = 0; j < 8; j++) bvals[j] = 0.f;
    }

    float* Cp = C + (long)g * cStride + (long)(blockRow + rowC) * N + ccol;
    const float* Rp = nullptr;
    if (Res) {
        long roff = (resMode == 1) ? (long)task * resStride : (long)g * resStride;
        Rp = Res + roff + (long)(blockRow + rowC) * N + ccol;
    }

#pragma unroll
    for (int i = 0; i < 8; i++) {
        float v[8];
#pragma unroll
        for (int j = 0; j < 4; j++) {
            float2 p = unpack2(acc[i][j]);
            v[2 * j]     = p.x + bvals[2 * j];
            v[2 * j + 1] = p.y + bvals[2 * j + 1];
        }
        if (Rp) {
            float4 r0 = *(const float4*)(Rp + (long)i * N);
            float4 r1 = *(const float4*)(Rp + (long)i * N + 4);
            v[0] += r0.x; v[1] += r0.y; v[2] += r0.z; v[3] += r0.w;
            v[4] += r1.x; v[5] += r1.y; v[6] += r1.z; v[7] += r1.w;
        }
        if (EPI == 1) {
#pragma unroll
            for (int j = 0; j < 8; j++)
                v[j] = 0.5f * v[j] * (1.0f + erff(v[j] * 0.70710678118654752440f));
        } else if (EPI == 2) {
#pragma unroll
            for (int j = 0; j < 8; j++) v[j] = fmaxf(v[j], 0.f);
        }
        float4 s0 = make_float4(v[0], v[1], v[2], v[3]);
        float4 s1 = make_float4(v[4], v[5], v[6], v[7]);
        *(float4*)(Cp + (long)i * N)     = s0;
        *(float4*)(Cp + (long)i * N + 4) = s1;
    }
}

// ---------------------------------------------------------------- fused LayerNorm: H = LN(H + Add) * gamma + beta
// grid: (Bb rows, NG groups), 128 threads, 4 elems each (Hdim = 512 fixed)
__global__ void ln_kernel(float* __restrict__ Hbuf, const float* __restrict__ Add,
                          const float* __restrict__ gamma, const float* __restrict__ beta,
                          long gStride)
{
    const int g   = blockIdx.y;
    const int row = blockIdx.x;
    const int e   = expert_of_group(g);
    const long off = ((long)g * Bb + row) * Hh;
    float* h = Hbuf + off;
    const int t = threadIdx.x;

    float4 hv = *(const float4*)&h[t * 4];
    if (Add) {
        float4 av = *(const float4*)&Add[off + t * 4];
        hv.x += av.x; hv.y += av.y; hv.z += av.z; hv.w += av.w;
    }
    float s = hv.x + hv.y + hv.z + hv.w;
    __shared__ float sh[8];
    const int wid = t >> 5, lane = t & 31;
    s = warp_sum(s);
    if (lane == 0) sh[wid] = s;
    __syncthreads();
    float tot = sh[0] + sh[1] + sh[2] + sh[3];
    float mean = tot * (1.0f / Hh);

    float d0 = hv.x - mean, d1 = hv.y - mean, d2 = hv.z - mean, d3 = hv.w - mean;
    float ss = d0 * d0 + d1 * d1 + d2 * d2 + d3 * d3;
    ss = warp_sum(ss);
    if (lane == 0) sh[4 + wid] = ss;
    __syncthreads();
    float var = (sh[4] + sh[5] + sh[6] + sh[7]) * (1.0f / Hh);
    float inv = rsqrtf(var + 1e-5f);

    const float* gm = gamma + (long)e * gStride;
    const float* bt = beta  + (long)e * gStride;
    float4 gv = *(const float4*)&gm[t * 4];
    float4 bv = *(const float4*)&bt[t * 4];
    float4 outv;
    outv.x = d0 * inv * gv.x + bv.x;
    outv.y = d1 * inv * gv.y + bv.y;
    outv.z = d2 * inv * gv.z + bv.z;
    outv.w = d3 * inv * gv.w + bv.w;
    *(float4*)&h[t * 4] = outv;
}

// ---------------------------------------------------------------- gate stage 2: logits = gh @ Wg2 + bg2, softmax
// one warp per (task,row); grid (Bb/4, Tt), 128 threads
__global__ void gate2_kernel(const float* __restrict__ gh, const float* __restrict__ Wg2,
                             const float* __restrict__ bg2, float* __restrict__ gate)
{
    const int i    = blockIdx.y;
    const int row  = blockIdx.x * 4 + (threadIdx.x >> 5);
    const int lane = threadIdx.x & 31;
    const float* g1 = gh + ((long)i * Bb + row) * Gg;
    const float  x0 = g1[lane];
    const float  x1 = g1[lane + 32];
    const float* w  = Wg2 + (long)i * Gg * NEe;

    float logits[NEe];
#pragma unroll
    for (int n = 0; n < NEe; n++) {
        float p = x0 * w[lane * NEe + n] + x1 * w[(lane + 32) * NEe + n];
        p = warp_sum(p);
        logits[n] = p + bg2[i * NEe + n];
    }
    float m = logits[0];
#pragma unroll
    for (int n = 1; n < NEe; n++) m = fmaxf(m, logits[n]);
    float ssum = 0.f;
#pragma unroll
    for (int n = 0; n < NEe; n++) { logits[n] = expf(logits[n] - m); ssum += logits[n]; }
    float rs = 1.0f / ssum;
    if (lane == 0) {
        float* gp = gate + ((long)i * Bb + row) * NEe;
#pragma unroll
        for (int n = 0; n < NEe; n++) gp[n] = logits[n] * rs;
    }
}

// ---------------------------------------------------------------- gated combine: cat[b, i*D+d] = sum_n o[i*6+n,b,d]*g[i,b,n]
__global__ void combine_kernel(const float* __restrict__ o, const float* __restrict__ gate,
                               float* __restrict__ cat)
{
    long idx = (long)blockIdx.x * blockDim.x + threadIdx.x;   // over Tt*Bb*Dd
    int d = (int)(idx % Dd);
    long bi = idx / Dd;
    int b = (int)(bi % Bb);
    int i = (int)(bi / Bb);
    const float* gp = gate + ((long)i * Bb + b) * NEe;
    float s = 0.f;
#pragma unroll
    for (int n = 0; n < NEe; n++)
        s += o[(((long)(i * NEe + n)) * Bb + b) * Hh + d] * gp[n];
    cat[(long)b * (Tt * Dd) + i * Dd + d] = s;
}

// ---------------------------------------------------------------- launch
extern "C" void kernel_launch(void* const* d_in, const int* in_sizes, int n_in,
                              void* d_out, int out_size)
{
    const float* x    = (const float*)d_in[0];
    const float* Win  = (const float*)d_in[1];
    const float* b_in = (const float*)d_in[2];
    const float* Wv   = (const float*)d_in[3];
    const float* bv   = (const float*)d_in[4];
    const float* Wo   = (const float*)d_in[5];
    const float* bo   = (const float*)d_in[6];
    const float* ln1g = (const float*)d_in[7];
    const float* ln1b = (const float*)d_in[8];
    const float* W1   = (const float*)d_in[9];
    const float* b1   = (const float*)d_in[10];
    const float* W2   = (const float*)d_in[11];
    const float* b2   = (const float*)d_in[12];
    const float* ln2g = (const float*)d_in[13];
    const float* ln2b = (const float*)d_in[14];
    const float* lnfg = (const float*)d_in[15];
    const float* lnfb = (const float*)d_in[16];
    const float* Wout = (const float*)d_in[17];
    const float* bout = (const float*)d_in[18];
    const float* Wg1  = (const float*)d_in[19];
    const float* bg1  = (const float*)d_in[20];
    const float* Wg2  = (const float*)d_in[21];
    const float* bg2  = (const float*)d_in[22];
    const float* Wf1  = (const float*)d_in[23];
    const float* bf1  = (const float*)d_in[24];
    const float* Wf2  = (const float*)d_in[25];
    const float* bf2  = (const float*)d_in[26];

    float *h, *t1, *t2, *f, *o, *gh, *gate, *cat, *fuse;
    cudaGetSymbolAddress((void**)&h,    g_h);
    cudaGetSymbolAddress((void**)&t1,   g_t1);
    cudaGetSymbolAddress((void**)&t2,   g_t2);
    cudaGetSymbolAddress((void**)&f,    g_f);
    cudaGetSymbolAddress((void**)&o,    g_o);
    cudaGetSymbolAddress((void**)&gh,   g_gh);
    cudaGetSymbolAddress((void**)&gate, g_gate);
    cudaGetSymbolAddress((void**)&cat,  g_cat);
    cudaGetSymbolAddress((void**)&fuse, g_fuse);

    const long GB = (long)Bb * Hh;   // per-group hidden stride
    const long GF = (long)Bb * Ff;

    dim3 blk(256);
    dim3 gHH(Hh / BN, Bb / BM, NG);   // (4, 32, 18)
    dim3 gHF(Ff / BN, Bb / BM, NG);   // (16, 32, 18)
    dim3 lnG(Bb, NG);

    // 1. input projection: h = x[task] @ Win[e] + b_in[e]
    gemm_kernel<0><<<gHH, blk>>>(x, (long)Bb * Dd, 1,
                                 Win, (long)Dd * Hh, 1, b_in, Hh,
                                 nullptr, 0, 0, h, GB, Bb, Hh, Dd);

    for (int l = 0; l < Ll; l++) {
        // v = h @ Wv + bv
        gemm_kernel<0><<<gHH, blk>>>(h, GB, 2,
                                     Wv + (long)l * Hh * Hh, (long)Ll * Hh * Hh, 1,
                                     bv + (long)l * Hh, (long)Ll * Hh,
                                     nullptr, 0, 0, t1, GB, Bb, Hh, Hh);
        // a = v @ Wo + bo
        gemm_kernel<0><<<gHH, blk>>>(t1, GB, 2,
                                     Wo + (long)l * Hh * Hh, (long)Ll * Hh * Hh, 1,
                                     bo + (long)l * Hh, (long)Ll * Hh,
                                     nullptr, 0, 0, t2, GB, Bb, Hh, Hh);
        // h = LN(h + a)
        ln_kernel<<<lnG, 128>>>(h, t2, ln1g + (long)l * Hh, ln1b + (long)l * Hh, (long)Ll * Hh);
        // f = gelu(h @ W1 + b1)
        gemm_kernel<1><<<gHF, blk>>>(h, GB, 2,
                                     W1 + (long)l * Hh * Ff, (long)Ll * Hh * Ff, 1,
                                     b1 + (long)l * Ff, (long)Ll * Ff,
                                     nullptr, 0, 0, f, GF, Bb, Ff, Hh);
        // t1 = f @ W2 + b2
        gemm_kernel<0><<<gHH, blk>>>(f, GF, 2,
                                     W2 + (long)l * Ff * Hh, (long)Ll * Ff * Hh, 1,
                                     b2 + (long)l * Hh, (long)Ll * Hh,
                                     nullptr, 0, 0, t1, GB, Bb, Hh, Ff);
        // h = LN(h + t1)
        ln_kernel<<<lnG, 128>>>(h, t1, ln2g + (long)l * Hh, ln2b + (long)l * Hh, (long)Ll * Hh);
    }

    // final norm
    ln_kernel<<<lnG, 128>>>(h, nullptr, lnfg, lnfb, (long)Hh);

    // o = h @ Wout + bout + x[task]
    gemm_kernel<0><<<gHH, blk>>>(h, GB, 2,
                                 Wout, (long)Hh * Dd, 1, bout, Dd,
                                 x, (long)Bb * Dd, 1, o, GB, Bb, Dd, Hh);

    // gate stage 1: gh = relu(x[i] @ Wg1[i] + bg1[i])
    gemm_kernel<2><<<dim3(1, Bb / BM, Tt), blk>>>(x, (long)Bb * Dd, 2,
                                                  Wg1, (long)Dd * Gg, 2, bg1, Gg,
                                                  nullptr, 0, 0, gh, (long)Bb * Gg,
                                                  Bb, Gg, Dd);
    // gate stage 2 + softmax
    gate2_kernel<<<dim3(Bb / 4, Tt), 128>>>(gh, Wg2, bg2, gate);

    // gated combine -> cat
    combine_kernel<<<(Tt * Bb * Dd) / 256, 256>>>(o, gate, cat);

    // fusion MLP
    gemm_kernel<2><<<dim3((2 * Dd) / BN, Bb / BM, 1), blk>>>(cat, 0, 0,
                                                             Wf1, 0, 0, bf1, 0,
                                                             nullptr, 0, 0, fuse, 0,
                                                             Bb, 2 * Dd, Tt * Dd);
    gemm_kernel<0><<<dim3(Dd / BN, Bb / BM, 1), blk>>>(fuse, 0, 0,
                                                       Wf2, 0, 0, bf2, 0,
                                                       nullptr, 0, 0, (float*)d_out, 0,
                                                       Bb, Dd, 2 * Dd);
}